// round 9
// baseline (speedup 1.0000x reference)
#include <cuda_runtime.h>
#include <cstdint>

// DCT per 8x8 patch: Z = C * M * C^T per strip, as two row-DCT passes with a
// smem transpose between. QUARTER-STRIP threads (2 rows each, 4 threads/strip)
// -> ~45 regs -> ~9 CTAs/SM (vs 92 regs / 5 CTAs for whole-strip threads).
// All coefficients FFMA immediates. 1024 FMA/strip unchanged.

#define THREADS     128
#define TILE_STRIPS 32                    // 4 threads per strip
#define TILE_F4     (TILE_STRIPS * 16)    // 512 float4 per tile
#define SD 20                             // D area: f4 stride per strip
#define ST 23                             // T area: f4 stride per strip

// 8-point DCT row transform, immediates: o[j] = sum_v a[v] * CT[v][j]
#define ROW_DCT(a, o)                                                                  \
    do {                                                                               \
        const float CT[8][8] = {                                                       \
            {0.353553391f, 0.353553391f, 0.353553391f, 0.353553391f,                   \
             0.353553391f, 0.353553391f, 0.353553391f, 0.353553391f},                  \
            {0.490392640f, 0.415734806f, 0.277785117f, 0.097545161f,                   \
             -0.097545161f, -0.277785117f, -0.415734806f, -0.490392640f},              \
            {0.461939766f, 0.191341716f, -0.191341716f, -0.461939766f,                 \
             -0.461939766f, -0.191341716f, 0.191341716f, 0.461939766f},                \
            {0.415734806f, -0.097545161f, -0.490392640f, -0.277785117f,                \
             0.277785117f, 0.490392640f, 0.097545161f, -0.415734806f},                 \
            {0.353553391f, -0.353553391f, -0.353553391f, 0.353553391f,                 \
             0.353553391f, -0.353553391f, -0.353553391f, 0.353553391f},                \
            {0.277785117f, -0.490392640f, 0.097545161f, 0.415734806f,                  \
             -0.415734806f, -0.097545161f, 0.490392640f, -0.277785117f},               \
            {0.191341716f, -0.461939766f, 0.461939766f, -0.191341716f,                 \
             -0.191341716f, 0.461939766f, -0.461939766f, 0.191341716f},                \
            {0.097545161f, -0.277785117f, 0.415734806f, -0.490392640f,                 \
             0.490392640f, -0.415734806f, 0.277785117f, -0.097545161f}};               \
        _Pragma("unroll")                                                              \
        for (int j = 0; j < 8; ++j) {                                                  \
            float acc = (a)[0] * CT[0][j];                                             \
            _Pragma("unroll")                                                          \
            for (int v = 1; v < 8; ++v) acc = fmaf((a)[v], CT[v][j], acc);             \
            (o)[j] = acc;                                                              \
        }                                                                              \
    } while (0)

__device__ __forceinline__ void cp_async16(float4* smem_dst, const float4* gsrc)
{
    uint32_t s = (uint32_t)__cvta_generic_to_shared(smem_dst);
    asm volatile("cp.async.cg.shared.global [%0], [%1], 16;\n" :: "r"(s), "l"(gsrc));
}
__device__ __forceinline__ void cp_commit() { asm volatile("cp.async.commit_group;\n" ::: "memory"); }
__device__ __forceinline__ void cp_wait0()  { asm volatile("cp.async.wait_group 0;\n" ::: "memory"); }

__global__ __launch_bounds__(THREADS)
void dct_quarter_kernel(const float4* __restrict__ in4, float4* __restrict__ out4)
{
    __shared__ float4 Dm[TILE_STRIPS * SD];   // strip data, gapped slots c+(c>>2)
    __shared__ float4 Tm[TILE_STRIPS * ST];   // transpose scratch, slots c+(c>>1)

    const int t = threadIdx.x;
    const size_t base = (size_t)blockIdx.x * TILE_F4;

    // ---- Phase 1: coalesced gmem -> D via cp.async ----
    const int c     = t & 15;
    const int slotD = c + (c >> 2);
#pragma unroll
    for (int k = 0; k < 4; ++k) {
        int strip = k * 8 + (t >> 4);
        cp_async16(&Dm[strip * SD + slotD], &in4[base + k * THREADS + t]);
    }
    cp_commit();
    cp_wait0();
    __syncthreads();

    const int s = t >> 2;       // strip (0..31)
    const int q = t & 3;        // quarter: rows 2q, 2q+1

    // ---- Pass A: row DCT on rows 2q,2q+1, write transposed to T ----
    {
        const float4* dp = &Dm[s * SD + q * 5];   // chunks 4q..4q+3, conflict-free
        float x[16];
#pragma unroll
        for (int k = 0; k < 4; ++k) {
            float4 v = dp[k];
            x[4 * k + 0] = v.x; x[4 * k + 1] = v.y;
            x[4 * k + 2] = v.z; x[4 * k + 3] = v.w;
        }
        float Y0[8], Y1[8];
        ROW_DCT(x, Y0);
        ROW_DCT(x + 8, Y1);

        // P^T[j][2q+r] = Y_r[j]  -> float2 {Y0[j], Y1[j]} at row j, cols 2q..2q+1
        float* tp = reinterpret_cast<float*>(Tm) + s * (ST * 4);
#pragma unroll
        for (int j = 0; j < 8; ++j) {
            int ch = 2 * j + (q >> 1);
            int fa = 4 * (ch + (ch >> 1)) + ((2 * q) & 3);
            *reinterpret_cast<float2*>(tp + fa) = make_float2(Y0[j], Y1[j]);
        }
    }
    __syncwarp();   // T readers/writers for strip s are the same 4 lanes (same warp)

    // ---- Pass B: row DCT on P^T rows 2q,2q+1 (= cols), write transposed to D ----
    {
        const float4* tp4 = Tm + s * ST;
        float p[16];
#pragma unroll
        for (int k = 0; k < 4; ++k) {
            int ch = 4 * q + k;
            float4 v = tp4[ch + (ch >> 1)];       // conflict-free (verified mod-8)
            p[4 * k + 0] = v.x; p[4 * k + 1] = v.y;
            p[4 * k + 2] = v.z; p[4 * k + 3] = v.w;
        }
        float Z0[8], Z1[8];
        ROW_DCT(p, Z0);        // Z0[i] = Z[i][2q]
        ROW_DCT(p + 8, Z1);    // Z1[i] = Z[i][2q+1]

        // Z[i][2q..2q+1] -> float2 at row i, cols 2q..2q+1 in D
        float* dpf = reinterpret_cast<float*>(Dm) + s * (SD * 4);
#pragma unroll
        for (int i = 0; i < 8; ++i) {
            int ch = 2 * i + (q >> 1);
            int fa = 4 * (ch + (ch >> 2)) + ((2 * q) & 3);
            *reinterpret_cast<float2*>(dpf + fa) = make_float2(Z0[i], Z1[i]);
        }
    }
    __syncthreads();

    // ---- Phase 3: coalesced D -> gmem ----
#pragma unroll
    for (int k = 0; k < 4; ++k) {
        int strip = k * 8 + (t >> 4);
        out4[base + k * THREADS + t] = Dm[strip * SD + slotD];
    }
}

// Tail (strip count not divisible by 32): direct per-thread whole-strip path.
__global__ void dct_tail_kernel(const float4* __restrict__ in4,
                                float4* __restrict__ out4,
                                int first_strip, int nstrips)
{
    int strip = first_strip + blockIdx.x * blockDim.x + threadIdx.x;
    if (strip >= nstrips) return;
    float x[64];
    const float4* ip = in4 + (size_t)strip * 16;
#pragma unroll
    for (int k = 0; k < 16; ++k) {
        float4 v = ip[k];
        x[4 * k + 0] = v.x; x[4 * k + 1] = v.y;
        x[4 * k + 2] = v.z; x[4 * k + 3] = v.w;
    }
    float y[64];
#pragma unroll
    for (int u = 0; u < 8; ++u) ROW_DCT(x + u * 8, y + u * 8);
#pragma unroll
    for (int j = 0; j < 8; ++j) {
        float a[8], o[8];
#pragma unroll
        for (int u = 0; u < 8; ++u) a[u] = y[u * 8 + j];
        ROW_DCT(a, o);
#pragma unroll
        for (int i = 0; i < 8; ++i) x[i * 8 + j] = o[i];
    }
    float4* op = out4 + (size_t)strip * 16;
#pragma unroll
    for (int k = 0; k < 16; ++k)
        op[k] = make_float4(x[4 * k + 0], x[4 * k + 1], x[4 * k + 2], x[4 * k + 3]);
}

extern "C" void kernel_launch(void* const* d_in, const int* in_sizes, int n_in,
                              void* d_out, int out_size)
{
    const float4* in4 = (const float4*)d_in[0];  // (8,3,1024,1024) fp32 contiguous
    float4* out4      = (float4*)d_out;

    int nstrips = in_sizes[0] / 64;              // 393216 on bench shape
    int ntiles  = nstrips / TILE_STRIPS;         // 12288

    if (ntiles > 0)
        dct_quarter_kernel<<<ntiles, THREADS>>>(in4, out4);
    int rem = nstrips - ntiles * TILE_STRIPS;
    if (rem > 0)
        dct_tail_kernel<<<(rem + 127) / 128, 128>>>(in4, out4,
                                                    ntiles * TILE_STRIPS, nstrips);
}

// round 10
// speedup vs baseline: 1.1161x; 1.1161x over previous
#include <cuda_runtime.h>
#include <cstdint>

// DCT per 8x8 patch == out(N,64) = X(N,64) @ (C ⊗ C), separable two-pass,
// 1024 FFMA-imm per strip. One tile (128 strips) per CTA, single smem buffer
// (R7 structure = fastest measured). R10 single change: output stores carry an
// L2::evict_first policy so the write stream stops evicting the (L2-sized)
// input between graph replays -> DRAM reads should collapse.

#define THREADS     128
#define TILE_STRIPS 128
#define TILE_F4     (TILE_STRIPS * 16)   // float4 per tile in gmem
#define PAD_F4      (TILE_STRIPS * 17)   // padded float4 per tile in smem

#define DCT_TABLE(CT)                                                                  \
    const float CT[8][8] = {                                                           \
        {0.353553391f, 0.353553391f, 0.353553391f, 0.353553391f,                       \
         0.353553391f, 0.353553391f, 0.353553391f, 0.353553391f},                      \
        {0.490392640f, 0.415734806f, 0.277785117f, 0.097545161f,                       \
         -0.097545161f, -0.277785117f, -0.415734806f, -0.490392640f},                  \
        {0.461939766f, 0.191341716f, -0.191341716f, -0.461939766f,                     \
         -0.461939766f, -0.191341716f, 0.191341716f, 0.461939766f},                    \
        {0.415734806f, -0.097545161f, -0.490392640f, -0.277785117f,                    \
         0.277785117f, 0.490392640f, 0.097545161f, -0.415734806f},                     \
        {0.353553391f, -0.353553391f, -0.353553391f, 0.353553391f,                     \
         0.353553391f, -0.353553391f, -0.353553391f, 0.353553391f},                    \
        {0.277785117f, -0.490392640f, 0.097545161f, 0.415734806f,                      \
         -0.415734806f, -0.097545161f, 0.490392640f, -0.277785117f},                   \
        {0.191341716f, -0.461939766f, 0.461939766f, -0.191341716f,                     \
         -0.191341716f, 0.461939766f, -0.461939766f, 0.191341716f},                    \
        {0.097545161f, -0.277785117f, 0.415734806f, -0.490392640f,                     \
         0.490392640f, -0.415734806f, 0.277785117f, -0.097545161f}};

__device__ __forceinline__ void cp_async16(float4* smem_dst, const float4* gsrc)
{
    uint32_t s = (uint32_t)__cvta_generic_to_shared(smem_dst);
    asm volatile("cp.async.cg.shared.global [%0], [%1], 16;\n" :: "r"(s), "l"(gsrc));
}
__device__ __forceinline__ void cp_commit() { asm volatile("cp.async.commit_group;\n" ::: "memory"); }
__device__ __forceinline__ void cp_wait0()  { asm volatile("cp.async.wait_group 0;\n" ::: "memory"); }

__device__ __forceinline__ uint64_t mk_evict_first_policy()
{
    uint64_t pol;
    asm("createpolicy.fractional.L2::evict_first.b64 %0, 1.0;" : "=l"(pol));
    return pol;
}
__device__ __forceinline__ void stg128_ef(float4* gdst, float4 v, uint64_t pol)
{
    asm volatile("st.global.L2::cache_hint.v4.f32 [%0], {%1, %2, %3, %4}, %5;\n"
                 :: "l"(gdst), "f"(v.x), "f"(v.y), "f"(v.z), "f"(v.w), "l"(pol)
                 : "memory");
}

__global__ __launch_bounds__(THREADS)
void dct_oneshot_kernel(const float4* __restrict__ in4, float4* __restrict__ out4)
{
    __shared__ float4 sm[PAD_F4];
    const int t    = threadIdx.x;
    const int trow = t >> 4;
    const int tcol = t & 15;
    const int pad_off = trow * 17 + tcol;

    const size_t base = (size_t)blockIdx.x * TILE_F4;

    // Coalesced gmem -> padded smem via cp.async (no register cost).
#pragma unroll
    for (int k = 0; k < 16; ++k)
        cp_async16(&sm[(k * 8) * 17 + pad_off], &in4[base + k * THREADS + t]);
    cp_commit();
    cp_wait0();
    __syncthreads();

    // Own strip: smem -> regs (conflict-free via stride-17 pad).
    float x[64];
    float4* sp = sm + t * 17;
#pragma unroll
    for (int k = 0; k < 16; ++k) {
        float4 v = sp[k];
        x[4 * k + 0] = v.x; x[4 * k + 1] = v.y;
        x[4 * k + 2] = v.z; x[4 * k + 3] = v.w;
    }

    DCT_TABLE(CT);
    // Stage 1 (in place): x[u*8+j] <- sum_v x[u*8+v] * CT[v][j]
#pragma unroll
    for (int u = 0; u < 8; ++u) {
        float tr[8];
#pragma unroll
        for (int j = 0; j < 8; ++j) {
            float a = x[u * 8 + 0] * CT[0][j];
#pragma unroll
            for (int v = 1; v < 8; ++v) a = fmaf(x[u * 8 + v], CT[v][j], a);
            tr[j] = a;
        }
#pragma unroll
        for (int j = 0; j < 8; ++j) x[u * 8 + j] = tr[j];
    }
    // Stage 2: row r streamed straight back to smem (in-place buffer reuse).
#pragma unroll
    for (int r = 0; r < 8; ++r) {
        float o[8];
#pragma unroll
        for (int j = 0; j < 8; ++j) {
            float a = x[0 * 8 + j] * CT[0][r];
#pragma unroll
            for (int u = 1; u < 8; ++u) a = fmaf(x[u * 8 + j], CT[u][r], a);
            o[j] = a;
        }
        sp[2 * r + 0] = make_float4(o[0], o[1], o[2], o[3]);
        sp[2 * r + 1] = make_float4(o[4], o[5], o[6], o[7]);
    }
    __syncthreads();

    // Coalesced smem -> gmem, output lines marked evict-first in L2
    // (write-once data; keeps the L2-sized input resident across replays).
    const uint64_t pol = mk_evict_first_policy();
#pragma unroll
    for (int k = 0; k < 16; ++k)
        stg128_ef(&out4[base + k * THREADS + t], sm[(k * 8) * 17 + pad_off], pol);
}

// Tail (strip count not divisible by 128): direct per-thread path, tiny.
__global__ void dct_tail_kernel(const float4* __restrict__ in4,
                                float4* __restrict__ out4,
                                int first_strip, int nstrips)
{
    int strip = first_strip + blockIdx.x * blockDim.x + threadIdx.x;
    if (strip >= nstrips) return;
    float x[64];
    const float4* ip = in4 + (size_t)strip * 16;
#pragma unroll
    for (int k = 0; k < 16; ++k) {
        float4 v = ip[k];
        x[4 * k + 0] = v.x; x[4 * k + 1] = v.y;
        x[4 * k + 2] = v.z; x[4 * k + 3] = v.w;
    }
    DCT_TABLE(CT);
#pragma unroll
    for (int u = 0; u < 8; ++u) {
        float tr[8];
#pragma unroll
        for (int j = 0; j < 8; ++j) {
            float a = x[u * 8 + 0] * CT[0][j];
#pragma unroll
            for (int v = 1; v < 8; ++v) a = fmaf(x[u * 8 + v], CT[v][j], a);
            tr[j] = a;
        }
#pragma unroll
        for (int j = 0; j < 8; ++j) x[u * 8 + j] = tr[j];
    }
    float4* op = out4 + (size_t)strip * 16;
#pragma unroll
    for (int r = 0; r < 8; ++r) {
        float o[8];
#pragma unroll
        for (int j = 0; j < 8; ++j) {
            float a = x[0 * 8 + j] * CT[0][r];
#pragma unroll
            for (int u = 1; u < 8; ++u) a = fmaf(x[u * 8 + j], CT[u][r], a);
            o[j] = a;
        }
        op[2 * r + 0] = make_float4(o[0], o[1], o[2], o[3]);
        op[2 * r + 1] = make_float4(o[4], o[5], o[6], o[7]);
    }
}

extern "C" void kernel_launch(void* const* d_in, const int* in_sizes, int n_in,
                              void* d_out, int out_size)
{
    const float4* in4 = (const float4*)d_in[0];  // (8,3,1024,1024) fp32 contiguous
    float4* out4      = (float4*)d_out;

    int nstrips = in_sizes[0] / 64;              // 393216 on bench shape
    int ntiles  = nstrips / TILE_STRIPS;         // 3072

    if (ntiles > 0)
        dct_oneshot_kernel<<<ntiles, THREADS>>>(in4, out4);
    int rem = nstrips - ntiles * TILE_STRIPS;
    if (rem > 0)
        dct_tail_kernel<<<(rem + 127) / 128, 128>>>(in4, out4,
                                                    ntiles * TILE_STRIPS, nstrips);
}

// round 12
// speedup vs baseline: 1.1242x; 1.0073x over previous
#include <cuda_runtime.h>
#include <cstdint>

// DCT per 8x8 patch == out(N,64) = X(N,64) @ (C ⊗ C), separable two-pass,
// 1024 FFMA-imm per strip. R11: ONE-WARP CTAs (32 threads, 32 strips, 8.7KB
// smem) -> ~22 resident CTAs/SM = 22 independent load/compute/store phase
// streams (vs 5 barrier-coupled ones in R7). Same per-thread instruction
// stream as the 31.5us kernel; only the concurrency structure changes.

#define THREADS     32
#define TILE_STRIPS 32
#define TILE_F4     (TILE_STRIPS * 16)   // 512 float4 per tile in gmem
#define PAD_F4      (TILE_STRIPS * 17)   // padded float4 per tile in smem

#define DCT_TABLE(CT)                                                                  \
    const float CT[8][8] = {                                                           \
        {0.353553391f, 0.353553391f, 0.353553391f, 0.353553391f,                       \
         0.353553391f, 0.353553391f, 0.353553391f, 0.353553391f},                      \
        {0.490392640f, 0.415734806f, 0.277785117f, 0.097545161f,                       \
         -0.097545161f, -0.277785117f, -0.415734806f, -0.490392640f},                  \
        {0.461939766f, 0.191341716f, -0.191341716f, -0.461939766f,                     \
         -0.461939766f, -0.191341716f, 0.191341716f, 0.461939766f},                    \
        {0.415734806f, -0.097545161f, -0.490392640f, -0.277785117f,                    \
         0.277785117f, 0.490392640f, 0.097545161f, -0.415734806f},                     \
        {0.353553391f, -0.353553391f, -0.353553391f, 0.353553391f,                     \
         0.353553391f, -0.353553391f, -0.353553391f, 0.353553391f},                    \
        {0.277785117f, -0.490392640f, 0.097545161f, 0.415734806f,                      \
         -0.415734806f, -0.097545161f, 0.490392640f, -0.277785117f},                   \
        {0.191341716f, -0.461939766f, 0.461939766f, -0.191341716f,                     \
         -0.191341716f, 0.461939766f, -0.461939766f, 0.191341716f},                    \
        {0.097545161f, -0.277785117f, 0.415734806f, -0.490392640f,                     \
         0.490392640f, -0.415734806f, 0.277785117f, -0.097545161f}};

__device__ __forceinline__ void cp_async16(float4* smem_dst, const float4* gsrc)
{
    uint32_t s = (uint32_t)__cvta_generic_to_shared(smem_dst);
    asm volatile("cp.async.cg.shared.global [%0], [%1], 16;\n" :: "r"(s), "l"(gsrc));
}
__device__ __forceinline__ void cp_commit() { asm volatile("cp.async.commit_group;\n" ::: "memory"); }
__device__ __forceinline__ void cp_wait0()  { asm volatile("cp.async.wait_group 0;\n" ::: "memory"); }

__device__ __forceinline__ uint64_t mk_evict_first_policy()
{
    uint64_t pol;
    asm("createpolicy.fractional.L2::evict_first.b64 %0, 1.0;" : "=l"(pol));
    return pol;
}
__device__ __forceinline__ void stg128_ef(float4* gdst, float4 v, uint64_t pol)
{
    asm volatile("st.global.L2::cache_hint.v4.f32 [%0], {%1, %2, %3, %4}, %5;\n"
                 :: "l"(gdst), "f"(v.x), "f"(v.y), "f"(v.z), "f"(v.w), "l"(pol)
                 : "memory");
}

__global__ __launch_bounds__(THREADS)
void dct_warp_cta_kernel(const float4* __restrict__ in4, float4* __restrict__ out4)
{
    __shared__ float4 sm[PAD_F4];
    const int t = threadIdx.x;
    // coalesced<->padded mapping for 32 strips: gmem f4 slot (k*32 + t) ->
    // strip 2k + (t>>4), chunk t&15; padded idx = strip*17 + chunk
    const int cslot = (t >> 4) * 17 + (t & 15);

    const size_t base = (size_t)blockIdx.x * TILE_F4;

    // Phase 1: coalesced gmem -> padded smem via cp.async.
#pragma unroll
    for (int k = 0; k < 16; ++k)
        cp_async16(&sm[2 * k * 17 + cslot], &in4[base + k * THREADS + t]);
    cp_commit();
    cp_wait0();
    __syncwarp();

    // Phase 2: own strip smem -> regs (conflict-free), transform, back to smem.
    float x[64];
    float4* sp = sm + t * 17;
#pragma unroll
    for (int k = 0; k < 16; ++k) {
        float4 v = sp[k];
        x[4 * k + 0] = v.x; x[4 * k + 1] = v.y;
        x[4 * k + 2] = v.z; x[4 * k + 3] = v.w;
    }

    DCT_TABLE(CT);
    // Stage 1 (in place): x[u*8+j] <- sum_v x[u*8+v] * CT[v][j]
#pragma unroll
    for (int u = 0; u < 8; ++u) {
        float tr[8];
#pragma unroll
        for (int j = 0; j < 8; ++j) {
            float a = x[u * 8 + 0] * CT[0][j];
#pragma unroll
            for (int v = 1; v < 8; ++v) a = fmaf(x[u * 8 + v], CT[v][j], a);
            tr[j] = a;
        }
#pragma unroll
        for (int j = 0; j < 8; ++j) x[u * 8 + j] = tr[j];
    }
    // Stage 2: row r streamed straight back to smem (in-place reuse).
#pragma unroll
    for (int r = 0; r < 8; ++r) {
        float o[8];
#pragma unroll
        for (int j = 0; j < 8; ++j) {
            float a = x[0 * 8 + j] * CT[0][r];
#pragma unroll
            for (int u = 1; u < 8; ++u) a = fmaf(x[u * 8 + j], CT[u][r], a);
            o[j] = a;
        }
        sp[2 * r + 0] = make_float4(o[0], o[1], o[2], o[3]);
        sp[2 * r + 1] = make_float4(o[4], o[5], o[6], o[7]);
    }
    __syncwarp();

    // Phase 3: coalesced smem -> gmem (output evict-first: neutral-to-best, R10).
    const uint64_t pol = mk_evict_first_policy();
#pragma unroll
    for (int k = 0; k < 16; ++k)
        stg128_ef(&out4[base + k * THREADS + t], sm[2 * k * 17 + cslot], pol);
}

// Tail (strip count not divisible by 32): direct per-thread path, tiny.
__global__ void dct_tail_kernel(const float4* __restrict__ in4,
                                float4* __restrict__ out4,
                                int first_strip, int nstrips)
{
    int strip = first_strip + blockIdx.x * blockDim.x + threadIdx.x;
    if (strip >= nstrips) return;
    float x[64];
    const float4* ip = in4 + (size_t)strip * 16;
#pragma unroll
    for (int k = 0; k < 16; ++k) {
        float4 v = ip[k];
        x[4 * k + 0] = v.x; x[4 * k + 1] = v.y;
        x[4 * k + 2] = v.z; x[4 * k + 3] = v.w;
    }
    DCT_TABLE(CT);
#pragma unroll
    for (int u = 0; u < 8; ++u) {
        float tr[8];
#pragma unroll
        for (int j = 0; j < 8; ++j) {
            float a = x[u * 8 + 0] * CT[0][j];
#pragma unroll
            for (int v = 1; v < 8; ++v) a = fmaf(x[u * 8 + v], CT[v][j], a);
            tr[j] = a;
        }
#pragma unroll
        for (int j = 0; j < 8; ++j) x[u * 8 + j] = tr[j];
    }
    float4* op = out4 + (size_t)strip * 16;
#pragma unroll
    for (int r = 0; r < 8; ++r) {
        float o[8];
#pragma unroll
        for (int j = 0; j < 8; ++j) {
            float a = x[0 * 8 + j] * CT[0][r];
#pragma unroll
            for (int u = 1; u < 8; ++u) a = fmaf(x[u * 8 + j], CT[u][r], a);
            o[j] = a;
        }
        op[2 * r + 0] = make_float4(o[0], o[1], o[2], o[3]);
        op[2 * r + 1] = make_float4(o[4], o[5], o[6], o[7]);
    }
}

extern "C" void kernel_launch(void* const* d_in, const int* in_sizes, int n_in,
                              void* d_out, int out_size)
{
    const float4* in4 = (const float4*)d_in[0];  // (8,3,1024,1024) fp32 contiguous
    float4* out4      = (float4*)d_out;

    int nstrips = in_sizes[0] / 64;              // 393216 on bench shape
    int ntiles  = nstrips / TILE_STRIPS;         // 12288

    if (ntiles > 0)
        dct_warp_cta_kernel<<<ntiles, THREADS>>>(in4, out4);
    int rem = nstrips - ntiles * TILE_STRIPS;
    if (rem > 0)
        dct_tail_kernel<<<(rem + 127) / 128, 128>>>(in4, out4,
                                                    ntiles * TILE_STRIPS, nstrips);
}